// round 14
// baseline (speedup 1.0000x reference)
#include <cuda_runtime.h>
#include <math.h>

#define N_TOT  8192
#define NF     8
#define HID    64
#define TILE   32
#define NTHR   128
#define NBLK   (N_TOT / TILE)   // 256
#define PIT    36               // smem row pitch (floats): 32 samples + 4 pad

typedef unsigned long long ull;

__device__ __forceinline__ float sigm(float x) {
    return 1.0f / (1.0f + __expf(-x));
}

// Accurate tanh (only where it feeds an output directly).
__device__ __forceinline__ float tanh_acc(float x) {
    float ax = fabsf(x);
    if (ax < 0.0625f) {
        float x2 = x * x;
        return x * (1.0f + x2 * (-0.33333333f + x2 * 0.13333334f));
    }
    float e = __expf(-2.0f * ax);
    float r = (1.0f - e) / (1.0f + e);
    return (x < 0.0f) ? -r : r;
}

// HW tanh approximation (MUFU.TANH) for hidden layers.
__device__ __forceinline__ float tanha(float x) {
    float r;
    asm("tanh.approx.f32 %0, %1;" : "=f"(r) : "f"(x));
    return r;
}

// Packed dual-lane FMA (sm_103a FFMA2; ptxas never emits from C++).
__device__ __forceinline__ ull fma2(ull a, ull b, ull c) {
    ull d;
    asm("fma.rn.f32x2 %0, %1, %2, %3;" : "=l"(d) : "l"(a), "l"(b), "l"(c));
    return d;
}
__device__ __forceinline__ float2 unpack2(ull v) {
    float2 r;
    asm("mov.b64 {%0, %1}, %2;" : "=f"(r.x), "=f"(r.y) : "l"(v));
    return r;
}
__device__ __forceinline__ ull dup2(float x) {
    ull d;
    asm("mov.b64 %0, {%1, %1};" : "=l"(d) : "f"(x));
    return d;
}

__device__ __forceinline__ unsigned smem_u32(const void* p) {
    return (unsigned)__cvta_generic_to_shared(p);
}
__device__ __forceinline__ void cp_async16(void* smem_dst, const void* gmem_src) {
    unsigned d = smem_u32(smem_dst);
    ull g = (ull)__cvta_generic_to_global(gmem_src);
    asm volatile("cp.async.ca.shared.global [%0], [%1], 16;" :: "r"(d), "l"(g));
}

// tanh 8 packed values -> 8 floats of one smem row starting at `row`
__device__ __forceinline__ void tanh_store8(float* row, ull a0, ull a1, ull a2, ull a3) {
    float2 u;
    u = unpack2(a0); *(float2*)&row[0] = make_float2(tanha(u.x), tanha(u.y));
    u = unpack2(a1); *(float2*)&row[2] = make_float2(tanha(u.x), tanha(u.y));
    u = unpack2(a2); *(float2*)&row[4] = make_float2(tanha(u.x), tanha(u.y));
    u = unpack2(a3); *(float2*)&row[6] = make_float2(tanha(u.x), tanha(u.y));
}

// ---------------------------------------------------------------------------
// Fused kernel: dual MLP (8->64->64->1) + quadrature + MIMICS epilogue.
// 256 blocks x 128 threads (4 warps), 32 samples/block.
// Each warp keeps the proven microtile (2 cols x 8 samples x 2 MLPs = 16
// FFMA2 chains) on ITS OWN 8 samples; all 4 warps share ONE cp.async-staged
// SMEM copy of W2 (32 KB) -> staging traffic halves vs R13 (8 MB total) and
// quadrature/layer-1 redundancy is amortized over 2x samples.
// H buffers REUSED for H2 (extra barrier) -> smem ~55 KB, 2 blocks/SM.
// Layer 3 uses two full warps (one per MLP); warp 0 reduces quadrature.
// Fast-math intrinsics for all staging/epilogue transcendentals.
// 128x32 orientation quadrature collapsed analytically to 3 theta moments
// (exact: uniform 32-pt phi-sum of cos^k, k<=4, equals continuous mean).
// ---------------------------------------------------------------------------
__global__ __launch_bounds__(NTHR)
void pinn_kernel(const float* __restrict__ X,
                 const float* __restrict__ theta,
                 const float* __restrict__ Wp1, const float* __restrict__ bp1,
                 const float* __restrict__ Wp2, const float* __restrict__ bp2,
                 const float* __restrict__ Wp3, const float* __restrict__ bp3,
                 const float* __restrict__ Wc1, const float* __restrict__ bc1,
                 const float* __restrict__ Wc2, const float* __restrict__ bc2,
                 const float* __restrict__ Wc3, const float* __restrict__ bc3,
                 const float* __restrict__ nb_raw, const float* __restrict__ nl_raw,
                 const float* __restrict__ so_raw, const float* __restrict__ mg_raw,
                 const float* __restrict__ s_raw,
                 float* __restrict__ out) {
    __shared__ __align__(16) float Wp2s[HID][HID];   // 16 KB staged weights
    __shared__ __align__(16) float Wc2s[HID][HID];   // 16 KB
    __shared__ __align__(16) float XT[NF][PIT];      // [feature][sample]
    __shared__ __align__(16) float Hp[HID][PIT];     // H1, reused as H2
    __shared__ __align__(16) float Hc[HID][PIT];
    __shared__ float qs[4][NTHR];
    __shared__ float qsum[4];
    __shared__ float Ys[2][TILE];

    const int t    = threadIdx.x;       // 0..127
    const int lane = t & 31;
    const int w    = t >> 5;            // warp id 0..3
    const int base = blockIdx.x * TILE;
    const float PI = 3.14159265358979f;

    // ---- issue W2 staging cp.asyncs FIRST (complete behind layer 1) ----
    {
        const float4* gp = (const float4*)Wp2;   // 1024 float4 each
        const float4* gc = (const float4*)Wc2;
        float4* sp = (float4*)&Wp2s[0][0];
        float4* sc = (float4*)&Wc2s[0][0];
        #pragma unroll
        for (int j = 0; j < 8; j++) {
            cp_async16(&sp[j * 128 + t], &gp[j * 128 + t]);
            cp_async16(&sc[j * 128 + t], &gc[j * 128 + t]);
        }
        asm volatile("cp.async.commit_group;" ::: "memory");
    }

    // ---- prefetch epilogue scalars + theta EARLY ----
    float pf_nb = 0.f, pf_nl = 0.f, pf_mg = 0.f, pf_s = 0.f, pf_th = 0.f;
    if (t < TILE) {
        pf_nb = nb_raw[0]; pf_nl = nl_raw[0];
        pf_mg = mg_raw[0]; pf_s  = s_raw[0];
        pf_th = theta[base + t];
    }

    // ---- stage: 1 quadrature point per thread + X (2 values/thread) ----
    {
        float sig_o = (10.0f + 70.0f * sigm(so_raw[0])) * (PI / 180.0f);
        float inv2s2 = 1.0f / (2.0f * sig_o * sig_o);
        float th  = (float)t * (PI * 0.5f / 127.0f);   // linspace(0,pi/2,128)
        float d   = th - PI * 0.25f;
        float sn, cn;
        __sincosf(th, &sn, &cn);
        float pdf = __expf(-d * d * inv2s2) * sn;
        float c2v = cn * cn, s2v = sn * sn;
        qs[0][t] = pdf;
        qs[1][t] = pdf * c2v * c2v;
        qs[2][t] = pdf * c2v * s2v;
        qs[3][t] = pdf * s2v * s2v;

        #pragma unroll
        for (int idx = t; idx < TILE * NF; idx += NTHR) {
            int r = idx >> 3, k = idx & 7;
            XT[k][r] = X[base * NF + idx];
        }
    }
    __syncthreads();

    // lane geometry: 2 adjacent columns, own 8 samples (4 packed pairs)
    const int c2  = 2 * lane;      // columns owned
    const int sgo = w * 8;         // first sample owned by this warp

    ull ap00, ap01, ap02, ap03, ap10, ap11, ap12, ap13;
    ull ac00, ac01, ac02, ac03, ac10, ac11, ac12, ac13;

    // ================= layer 1 (both MLPs): K = 8 =================
    {
        float2 bp = __ldg((const float2*)(bp1 + c2));
        float2 bc = __ldg((const float2*)(bc1 + c2));
        ull b;
        b = dup2(bp.x); ap00 = b; ap01 = b; ap02 = b; ap03 = b;
        b = dup2(bp.y); ap10 = b; ap11 = b; ap12 = b; ap13 = b;
        b = dup2(bc.x); ac00 = b; ac01 = b; ac02 = b; ac03 = b;
        b = dup2(bc.y); ac10 = b; ac11 = b; ac12 = b; ac13 = b;
        #pragma unroll
        for (int k = 0; k < NF; k++) {
            ulonglong2 A0 = *(const ulonglong2*)&XT[k][sgo];       // pairs 0,1
            ulonglong2 A1 = *(const ulonglong2*)&XT[k][sgo + 4];   // pairs 2,3
            float2 wpv = __ldg((const float2*)(Wp1 + k * HID + c2));
            float2 wcv = __ldg((const float2*)(Wc1 + k * HID + c2));
            ull wp0 = dup2(wpv.x), wp1 = dup2(wpv.y);
            ull wc0 = dup2(wcv.x), wc1 = dup2(wcv.y);
            ap00 = fma2(A0.x, wp0, ap00); ap01 = fma2(A0.y, wp0, ap01);
            ap02 = fma2(A1.x, wp0, ap02); ap03 = fma2(A1.y, wp0, ap03);
            ap10 = fma2(A0.x, wp1, ap10); ap11 = fma2(A0.y, wp1, ap11);
            ap12 = fma2(A1.x, wp1, ap12); ap13 = fma2(A1.y, wp1, ap13);
            ac00 = fma2(A0.x, wc0, ac00); ac01 = fma2(A0.y, wc0, ac01);
            ac02 = fma2(A1.x, wc0, ac02); ac03 = fma2(A1.y, wc0, ac03);
            ac10 = fma2(A0.x, wc1, ac10); ac11 = fma2(A0.y, wc1, ac11);
            ac12 = fma2(A1.x, wc1, ac12); ac13 = fma2(A1.y, wc1, ac13);
        }
        tanh_store8(&Hp[c2    ][sgo], ap00, ap01, ap02, ap03);
        tanh_store8(&Hp[c2 + 1][sgo], ap10, ap11, ap12, ap13);
        tanh_store8(&Hc[c2    ][sgo], ac00, ac01, ac02, ac03);
        tanh_store8(&Hc[c2 + 1][sgo], ac10, ac11, ac12, ac13);
    }
    // W2 staging must be complete and H1 visible before layer 2
    asm volatile("cp.async.wait_group 0;" ::: "memory");
    __syncthreads();

    // ==== layer 2 (both MLPs): K = 64, weights from SMEM (zero gmem) ====
    {
        float2 bp = __ldg((const float2*)(bp2 + c2));
        float2 bc = __ldg((const float2*)(bc2 + c2));
        ull b;
        b = dup2(bp.x); ap00 = b; ap01 = b; ap02 = b; ap03 = b;
        b = dup2(bp.y); ap10 = b; ap11 = b; ap12 = b; ap13 = b;
        b = dup2(bc.x); ac00 = b; ac01 = b; ac02 = b; ac03 = b;
        b = dup2(bc.y); ac10 = b; ac11 = b; ac12 = b; ac13 = b;

        // distance-1 prefetch: weights + activations
        float2 nWp = *(const float2*)&Wp2s[0][c2];
        float2 nWc = *(const float2*)&Wc2s[0][c2];
        ulonglong2 nAp0 = *(const ulonglong2*)&Hp[0][sgo];
        ulonglong2 nAp1 = *(const ulonglong2*)&Hp[0][sgo + 4];
        ulonglong2 nAc0 = *(const ulonglong2*)&Hc[0][sgo];
        ulonglong2 nAc1 = *(const ulonglong2*)&Hc[0][sgo + 4];

        #pragma unroll 8
        for (int k = 0; k < HID; k++) {
            ull wp0 = dup2(nWp.x), wp1 = dup2(nWp.y);
            ull wc0 = dup2(nWc.x), wc1 = dup2(nWc.y);
            ulonglong2 Ap0 = nAp0, Ap1 = nAp1, Ac0 = nAc0, Ac1 = nAc1;
            if (k + 1 < HID) {
                nWp  = *(const float2*)&Wp2s[k + 1][c2];
                nWc  = *(const float2*)&Wc2s[k + 1][c2];
                nAp0 = *(const ulonglong2*)&Hp[k + 1][sgo];
                nAp1 = *(const ulonglong2*)&Hp[k + 1][sgo + 4];
                nAc0 = *(const ulonglong2*)&Hc[k + 1][sgo];
                nAc1 = *(const ulonglong2*)&Hc[k + 1][sgo + 4];
            }
            ap00 = fma2(Ap0.x, wp0, ap00); ap01 = fma2(Ap0.y, wp0, ap01);
            ap02 = fma2(Ap1.x, wp0, ap02); ap03 = fma2(Ap1.y, wp0, ap03);
            ap10 = fma2(Ap0.x, wp1, ap10); ap11 = fma2(Ap0.y, wp1, ap11);
            ap12 = fma2(Ap1.x, wp1, ap12); ap13 = fma2(Ap1.y, wp1, ap13);
            ac00 = fma2(Ac0.x, wc0, ac00); ac01 = fma2(Ac0.y, wc0, ac01);
            ac02 = fma2(Ac1.x, wc0, ac02); ac03 = fma2(Ac1.y, wc0, ac03);
            ac10 = fma2(Ac0.x, wc1, ac10); ac11 = fma2(Ac0.y, wc1, ac11);
            ac12 = fma2(Ac1.x, wc1, ac12); ac13 = fma2(Ac1.y, wc1, ac13);
        }
    }
    __syncthreads();   // ALL warps done reading H1: safe to overwrite
    tanh_store8(&Hp[c2    ][sgo], ap00, ap01, ap02, ap03);
    tanh_store8(&Hp[c2 + 1][sgo], ap10, ap11, ap12, ap13);
    tanh_store8(&Hc[c2    ][sgo], ac00, ac01, ac02, ac03);
    tanh_store8(&Hc[c2 + 1][sgo], ac10, ac11, ac12, ac13);
    __syncthreads();   // H2 (all 32 samples) visible

    // ---- parallel: warp 0 reduces quadrature; warps 1,2 do layer 3 ----
    if (w == 0) {
        #pragma unroll
        for (int a = 0; a < 4; a++) {
            float v = qs[a][lane] + qs[a][lane + 32]
                    + qs[a][lane + 64] + qs[a][lane + 96];
            v += __shfl_xor_sync(0xFFFFFFFF, v, 16);
            v += __shfl_xor_sync(0xFFFFFFFF, v, 8);
            v += __shfl_xor_sync(0xFFFFFFFF, v, 4);
            v += __shfl_xor_sync(0xFFFFFFFF, v, 2);
            v += __shfl_xor_sync(0xFFFFFFFF, v, 1);
            if (lane == 0) qsum[a] = v;
        }
    } else if (w <= 2) {
        // warp 1: MLP p, warp 2: MLP c — 32 dots each, 1 lane per sample
        int mlp = w - 1, rr = lane;
        const float* W3 = mlp ? Wc3 : Wp3;
        const float* H2 = mlp ? &Hc[0][0] : &Hp[0][0];
        float v0 = __ldg(mlp ? bc3 : bp3);
        float v1 = 0.f, v2 = 0.f, v3 = 0.f;
        #pragma unroll 4
        for (int k = 0; k < HID; k += 4) {
            v0 = fmaf(H2[(k + 0) * PIT + rr], __ldg(W3 + k + 0), v0);
            v1 = fmaf(H2[(k + 1) * PIT + rr], __ldg(W3 + k + 1), v1);
            v2 = fmaf(H2[(k + 2) * PIT + rr], __ldg(W3 + k + 2), v2);
            v3 = fmaf(H2[(k + 3) * PIT + rr], __ldg(W3 + k + 3), v3);
        }
        Ys[mlp][rr] = (v0 + v1) + (v2 + v3);
    }
    __syncthreads();

    // ---- epilogue: MIMICS physics, analytically reduced quadrature ----
    if (t < TILE) {
        int s = base + t;

        float inv = 1.0f / qsum[0];
        float S1 = qsum[1] * inv, S2 = qsum[2] * inv, S3 = qsum[3] * inv;

        const float LN10 = 2.302585093f;
        float Nb = __expf((2.0f + 3.0f * sigm(pf_nb)) * LN10);
        float Nl = __expf((3.0f + 3.0f * sigm(pf_nl)) * LN10);
        float dens = Nb * 1e-4f + Nl * 1e-6f;

        float mg   = 0.05f + 0.75f * sigm(pf_mg);
        float epsv = 1.5f + 20.0f * mg;
        float Kv   = (epsv - 1.0f) / (epsv + 2.0f);
        float Kv2  = Kv * Kv;

        float sm = 0.01f * (0.5f + 5.5f * sigm(pf_s));
        float kw = 2.0f * PI * (5.405e9f / 2.998e8f);
        float tt = 2.0f * kw * sm;
        float c_r = tt * tt;

        float m_v   = 0.93f * sigm(Ys[0][t]);
        float delta = 0.05f * tanh_acc(Ys[1][t]);   // direct output: exact tanh
        float eps_g = 3.0f + 25.0f * m_v + 10.0f * m_v * m_v;

        float ti = pf_th * (PI / 180.0f);
        float ct, st;
        __sincosf(ti, &st, &ct);
        float ct2 = ct * ct, st2 = st * st;

        float crown_vv = Kv2 * (ct2 * ct2 * S1 + 3.0f * ct2 * st2 * S2
                                + 0.375f * st2 * st2 * S3);
        float crown_vh = Kv2 * (0.5f * ct2 * S2 + 0.125f * st2 * S3);

        float root  = sqrtf(eps_g - st2);
        float r_v   = (eps_g * ct - root) / (eps_g * ct + root);
        float gamma = r_v * r_v;
        float rough = __expf(-c_r * ct2);
        float ground = gamma * rough * ct2;

        float svv = dens * crown_vv + ground;
        float svh = dens * crown_vh + 0.05f * ground;

        const float ILN10_10 = 4.342944819f;   // 10 / ln(10)
        out[0 * N_TOT + s] = m_v;
        out[1 * N_TOT + s] = delta;
        out[2 * N_TOT + s] = m_v + delta;
        out[3 * N_TOT + s] = __logf(svv + 1e-12f) * ILN10_10;
        out[4 * N_TOT + s] = __logf(svh + 1e-12f) * ILN10_10;
        out[5 * N_TOT + s] = eps_g;
    }
}

extern "C" void kernel_launch(void* const* d_in, const int* in_sizes, int n_in,
                              void* d_out, int out_size) {
    // inputs: 0 X, 1 theta_inc_deg, 2 vv_db_observed (unused),
    // 3 Wp1, 4 bp1, 5 Wp2, 6 bp2, 7 Wp3, 8 bp3,
    // 9 Wc1, 10 bc1, 11 Wc2, 12 bc2, 13 Wc3, 14 bc3,
    // 15 nb_raw, 16 nl_raw, 17 so_raw, 18 mg_raw, 19 s_raw
    (void)in_sizes; (void)n_in; (void)out_size;

    pinn_kernel<<<NBLK, NTHR>>>(
        (const float*)d_in[0], (const float*)d_in[1],
        (const float*)d_in[3], (const float*)d_in[4],
        (const float*)d_in[5], (const float*)d_in[6],
        (const float*)d_in[7], (const float*)d_in[8],
        (const float*)d_in[9], (const float*)d_in[10],
        (const float*)d_in[11], (const float*)d_in[12],
        (const float*)d_in[13], (const float*)d_in[14],
        (const float*)d_in[15], (const float*)d_in[16],
        (const float*)d_in[17], (const float*)d_in[18],
        (const float*)d_in[19],
        (float*)d_out);
}

// round 15
// speedup vs baseline: 1.0201x; 1.0201x over previous
#include <cuda_runtime.h>
#include <math.h>

#define N_TOT  8192
#define NF     8
#define HID    64
#define TILE   32
#define NTHR   128
#define NBLK   (N_TOT / TILE)   // 256
#define PIT    36               // H row pitch (floats): 32 samples + 4 pad
#define WPIT   128              // dup'd weight row pitch (floats)

typedef unsigned long long ull;

__device__ __forceinline__ float sigm(float x) {
    return 1.0f / (1.0f + __expf(-x));
}

// Accurate tanh (only where it feeds an output directly).
__device__ __forceinline__ float tanh_acc(float x) {
    float ax = fabsf(x);
    if (ax < 0.0625f) {
        float x2 = x * x;
        return x * (1.0f + x2 * (-0.33333333f + x2 * 0.13333334f));
    }
    float e = __expf(-2.0f * ax);
    float r = (1.0f - e) / (1.0f + e);
    return (x < 0.0f) ? -r : r;
}

// HW tanh approximation (MUFU.TANH) for hidden layers.
__device__ __forceinline__ float tanha(float x) {
    float r;
    asm("tanh.approx.f32 %0, %1;" : "=f"(r) : "f"(x));
    return r;
}

// Packed dual-lane FMA (sm_103a FFMA2; ptxas never emits from C++).
__device__ __forceinline__ ull fma2(ull a, ull b, ull c) {
    ull d;
    asm("fma.rn.f32x2 %0, %1, %2, %3;" : "=l"(d) : "l"(a), "l"(b), "l"(c));
    return d;
}
__device__ __forceinline__ float2 unpack2(ull v) {
    float2 r;
    asm("mov.b64 {%0, %1}, %2;" : "=f"(r.x), "=f"(r.y) : "l"(v));
    return r;
}
__device__ __forceinline__ ull dup2(float x) {
    ull d;
    asm("mov.b64 %0, {%1, %1};" : "=l"(d) : "f"(x));
    return d;
}

// tanh 8 packed values -> 8 floats of one smem row starting at `row`
__device__ __forceinline__ void tanh_store8(float* row, ull a0, ull a1, ull a2, ull a3) {
    float2 u;
    u = unpack2(a0); *(float2*)&row[0] = make_float2(tanha(u.x), tanha(u.y));
    u = unpack2(a1); *(float2*)&row[2] = make_float2(tanha(u.x), tanha(u.y));
    u = unpack2(a2); *(float2*)&row[4] = make_float2(tanha(u.x), tanha(u.y));
    u = unpack2(a3); *(float2*)&row[6] = make_float2(tanha(u.x), tanha(u.y));
}

// ---------------------------------------------------------------------------
// Fused kernel: dual MLP (8->64->64->1) + quadrature + MIMICS epilogue.
// 256 blocks x 128 threads (4 warps), 32 samples/block.
// Warp microtile: 2 cols x 8 samples x 2 MLPs = 16 FFMA2 chains.
// NEW vs R14: layer-2 weights staged PRE-DUPLICATED in smem
// (Wdup[k] = w0,w0,w1,w1,...) so the hot loop is 2 LDS.128 (weights, both
// packed b-operands directly) + 4 LDS.128 (acts) + 16 FFMA2 = 22 slots/iter
// (was 26 with 4 dup movs + 2 LDS.64). Staging: LDG.128 at kernel top ->
// dup in regs -> STS.128, overlapped with quadrature/XT math.
// Each warp writes/reads only its own samples of H -> layer1->layer2 and the
// in-place H1->H2 overwrite need only __syncwarp(); 2 block barriers total.
// 128x32 orientation quadrature collapsed analytically to 3 theta moments
// (exact: uniform 32-pt phi-sum of cos^k, k<=4, equals continuous mean).
// ---------------------------------------------------------------------------
__global__ __launch_bounds__(NTHR)
void pinn_kernel(const float* __restrict__ X,
                 const float* __restrict__ theta,
                 const float* __restrict__ Wp1, const float* __restrict__ bp1,
                 const float* __restrict__ Wp2, const float* __restrict__ bp2,
                 const float* __restrict__ Wp3, const float* __restrict__ bp3,
                 const float* __restrict__ Wc1, const float* __restrict__ bc1,
                 const float* __restrict__ Wc2, const float* __restrict__ bc2,
                 const float* __restrict__ Wc3, const float* __restrict__ bc3,
                 const float* __restrict__ nb_raw, const float* __restrict__ nl_raw,
                 const float* __restrict__ so_raw, const float* __restrict__ mg_raw,
                 const float* __restrict__ s_raw,
                 float* __restrict__ out) {
    __shared__ __align__(16) float Wp2s[HID][WPIT];  // 32 KB dup'd weights
    __shared__ __align__(16) float Wc2s[HID][WPIT];  // 32 KB
    __shared__ __align__(16) float XT[NF][PIT];      // [feature][sample]
    __shared__ __align__(16) float Hp[HID][PIT];     // H1, reused as H2
    __shared__ __align__(16) float Hc[HID][PIT];
    __shared__ float qs[4][NTHR];
    __shared__ float qsum[4];
    __shared__ float Ys[2][TILE];

    const int t    = threadIdx.x;       // 0..127
    const int lane = t & 31;
    const int w    = t >> 5;            // warp id 0..3
    const int base = blockIdx.x * TILE;
    const float PI = 3.14159265358979f;

    // ---- issue W2 LDGs FIRST (latency overlapped with quadrature/XT) ----
    float4 WP[8], WC[8];
    {
        const float4* gp = (const float4*)Wp2;   // 1024 float4 each
        const float4* gc = (const float4*)Wc2;
        #pragma unroll
        for (int i = 0; i < 8; i++) {
            WP[i] = __ldg(&gp[t + 128 * i]);
            WC[i] = __ldg(&gc[t + 128 * i]);
        }
    }

    // ---- prefetch epilogue scalars + theta EARLY ----
    float pf_nb = 0.f, pf_nl = 0.f, pf_mg = 0.f, pf_s = 0.f, pf_th = 0.f;
    if (t < TILE) {
        pf_nb = nb_raw[0]; pf_nl = nl_raw[0];
        pf_mg = mg_raw[0]; pf_s  = s_raw[0];
        pf_th = theta[base + t];
    }

    // ---- stage: 1 quadrature point per thread + X ----
    {
        float sig_o = (10.0f + 70.0f * sigm(so_raw[0])) * (PI / 180.0f);
        float inv2s2 = 1.0f / (2.0f * sig_o * sig_o);
        float th  = (float)t * (PI * 0.5f / 127.0f);   // linspace(0,pi/2,128)
        float d   = th - PI * 0.25f;
        float sn, cn;
        __sincosf(th, &sn, &cn);
        float pdf = __expf(-d * d * inv2s2) * sn;
        float c2v = cn * cn, s2v = sn * sn;
        qs[0][t] = pdf;
        qs[1][t] = pdf * c2v * c2v;
        qs[2][t] = pdf * c2v * s2v;
        qs[3][t] = pdf * s2v * s2v;

        #pragma unroll
        for (int idx = t; idx < TILE * NF; idx += NTHR) {
            int r = idx >> 3, k = idx & 7;
            XT[k][r] = X[base * NF + idx];
        }
    }

    // ---- duplicate + store W2 into smem ----
    {
        #pragma unroll
        for (int i = 0; i < 8; i++) {
            int j  = t + 128 * i;        // float4 index in [0,1024)
            int k  = j >> 4;             // weight row
            int cg = j & 15;             // 4-col group
            float4 v = WP[i];
            *(float4*)&Wp2s[k][8 * cg    ] = make_float4(v.x, v.x, v.y, v.y);
            *(float4*)&Wp2s[k][8 * cg + 4] = make_float4(v.z, v.z, v.w, v.w);
            v = WC[i];
            *(float4*)&Wc2s[k][8 * cg    ] = make_float4(v.x, v.x, v.y, v.y);
            *(float4*)&Wc2s[k][8 * cg + 4] = make_float4(v.z, v.z, v.w, v.w);
        }
    }
    __syncthreads();   // XT + qs + Wdup visible

    // lane geometry: 2 adjacent columns, own 8 samples (4 packed pairs)
    const int c2  = 2 * lane;      // columns owned
    const int sgo = w * 8;         // first sample owned by this warp

    ull ap00, ap01, ap02, ap03, ap10, ap11, ap12, ap13;
    ull ac00, ac01, ac02, ac03, ac10, ac11, ac12, ac13;

    // ================= layer 1 (both MLPs): K = 8 =================
    {
        float2 bp = __ldg((const float2*)(bp1 + c2));
        float2 bc = __ldg((const float2*)(bc1 + c2));
        ull b;
        b = dup2(bp.x); ap00 = b; ap01 = b; ap02 = b; ap03 = b;
        b = dup2(bp.y); ap10 = b; ap11 = b; ap12 = b; ap13 = b;
        b = dup2(bc.x); ac00 = b; ac01 = b; ac02 = b; ac03 = b;
        b = dup2(bc.y); ac10 = b; ac11 = b; ac12 = b; ac13 = b;
        #pragma unroll
        for (int k = 0; k < NF; k++) {
            ulonglong2 A0 = *(const ulonglong2*)&XT[k][sgo];       // pairs 0,1
            ulonglong2 A1 = *(const ulonglong2*)&XT[k][sgo + 4];   // pairs 2,3
            float2 wpv = __ldg((const float2*)(Wp1 + k * HID + c2));
            float2 wcv = __ldg((const float2*)(Wc1 + k * HID + c2));
            ull wp0 = dup2(wpv.x), wp1 = dup2(wpv.y);
            ull wc0 = dup2(wcv.x), wc1 = dup2(wcv.y);
            ap00 = fma2(A0.x, wp0, ap00); ap01 = fma2(A0.y, wp0, ap01);
            ap02 = fma2(A1.x, wp0, ap02); ap03 = fma2(A1.y, wp0, ap03);
            ap10 = fma2(A0.x, wp1, ap10); ap11 = fma2(A0.y, wp1, ap11);
            ap12 = fma2(A1.x, wp1, ap12); ap13 = fma2(A1.y, wp1, ap13);
            ac00 = fma2(A0.x, wc0, ac00); ac01 = fma2(A0.y, wc0, ac01);
            ac02 = fma2(A1.x, wc0, ac02); ac03 = fma2(A1.y, wc0, ac03);
            ac10 = fma2(A0.x, wc1, ac10); ac11 = fma2(A0.y, wc1, ac11);
            ac12 = fma2(A1.x, wc1, ac12); ac13 = fma2(A1.y, wc1, ac13);
        }
        tanh_store8(&Hp[c2    ][sgo], ap00, ap01, ap02, ap03);
        tanh_store8(&Hp[c2 + 1][sgo], ap10, ap11, ap12, ap13);
        tanh_store8(&Hc[c2    ][sgo], ac00, ac01, ac02, ac03);
        tanh_store8(&Hc[c2 + 1][sgo], ac10, ac11, ac12, ac13);
    }
    __syncwarp();   // warp-private H samples: warp-level sync suffices

    // ==== layer 2 (both MLPs): K = 64, dup'd weights from SMEM ====
    {
        float2 bp = __ldg((const float2*)(bp2 + c2));
        float2 bc = __ldg((const float2*)(bc2 + c2));
        ull b;
        b = dup2(bp.x); ap00 = b; ap01 = b; ap02 = b; ap03 = b;
        b = dup2(bp.y); ap10 = b; ap11 = b; ap12 = b; ap13 = b;
        b = dup2(bc.x); ac00 = b; ac01 = b; ac02 = b; ac03 = b;
        b = dup2(bc.y); ac10 = b; ac11 = b; ac12 = b; ac13 = b;

        // distance-1 prefetch: dup'd weights + activations
        ulonglong2 nWp = *(const ulonglong2*)&Wp2s[0][4 * lane];
        ulonglong2 nWc = *(const ulonglong2*)&Wc2s[0][4 * lane];
        ulonglong2 nAp0 = *(const ulonglong2*)&Hp[0][sgo];
        ulonglong2 nAp1 = *(const ulonglong2*)&Hp[0][sgo + 4];
        ulonglong2 nAc0 = *(const ulonglong2*)&Hc[0][sgo];
        ulonglong2 nAc1 = *(const ulonglong2*)&Hc[0][sgo + 4];

        #pragma unroll 8
        for (int k = 0; k < HID; k++) {
            ull wp0 = nWp.x, wp1 = nWp.y;
            ull wc0 = nWc.x, wc1 = nWc.y;
            ulonglong2 Ap0 = nAp0, Ap1 = nAp1, Ac0 = nAc0, Ac1 = nAc1;
            if (k + 1 < HID) {
                nWp  = *(const ulonglong2*)&Wp2s[k + 1][4 * lane];
                nWc  = *(const ulonglong2*)&Wc2s[k + 1][4 * lane];
                nAp0 = *(const ulonglong2*)&Hp[k + 1][sgo];
                nAp1 = *(const ulonglong2*)&Hp[k + 1][sgo + 4];
                nAc0 = *(const ulonglong2*)&Hc[k + 1][sgo];
                nAc1 = *(const ulonglong2*)&Hc[k + 1][sgo + 4];
            }
            ap00 = fma2(Ap0.x, wp0, ap00); ap01 = fma2(Ap0.y, wp0, ap01);
            ap02 = fma2(Ap1.x, wp0, ap02); ap03 = fma2(Ap1.y, wp0, ap03);
            ap10 = fma2(Ap0.x, wp1, ap10); ap11 = fma2(Ap0.y, wp1, ap11);
            ap12 = fma2(Ap1.x, wp1, ap12); ap13 = fma2(Ap1.y, wp1, ap13);
            ac00 = fma2(Ac0.x, wc0, ac00); ac01 = fma2(Ac0.y, wc0, ac01);
            ac02 = fma2(Ac1.x, wc0, ac02); ac03 = fma2(Ac1.y, wc0, ac03);
            ac10 = fma2(Ac0.x, wc1, ac10); ac11 = fma2(Ac0.y, wc1, ac11);
            ac12 = fma2(Ac1.x, wc1, ac12); ac13 = fma2(Ac1.y, wc1, ac13);
        }
    }
    __syncwarp();   // this warp done reading its H1 samples: overwrite OK
    tanh_store8(&Hp[c2    ][sgo], ap00, ap01, ap02, ap03);
    tanh_store8(&Hp[c2 + 1][sgo], ap10, ap11, ap12, ap13);
    tanh_store8(&Hc[c2    ][sgo], ac00, ac01, ac02, ac03);
    tanh_store8(&Hc[c2 + 1][sgo], ac10, ac11, ac12, ac13);
    __syncthreads();   // H2 (all 32 samples) visible to layer-3 warps

    // ---- parallel: warp 0 reduces quadrature; warps 1,2 do layer 3 ----
    if (w == 0) {
        #pragma unroll
        for (int a = 0; a < 4; a++) {
            float v = qs[a][lane] + qs[a][lane + 32]
                    + qs[a][lane + 64] + qs[a][lane + 96];
            v += __shfl_xor_sync(0xFFFFFFFF, v, 16);
            v += __shfl_xor_sync(0xFFFFFFFF, v, 8);
            v += __shfl_xor_sync(0xFFFFFFFF, v, 4);
            v += __shfl_xor_sync(0xFFFFFFFF, v, 2);
            v += __shfl_xor_sync(0xFFFFFFFF, v, 1);
            if (lane == 0) qsum[a] = v;
        }
    } else if (w <= 2) {
        // warp 1: MLP p, warp 2: MLP c — 32 dots each, 1 lane per sample
        int mlp = w - 1, rr = lane;
        const float* W3 = mlp ? Wc3 : Wp3;
        const float* H2 = mlp ? &Hc[0][0] : &Hp[0][0];
        float v0 = __ldg(mlp ? bc3 : bp3);
        float v1 = 0.f, v2 = 0.f, v3 = 0.f;
        #pragma unroll 4
        for (int k = 0; k < HID; k += 4) {
            v0 = fmaf(H2[(k + 0) * PIT + rr], __ldg(W3 + k + 0), v0);
            v1 = fmaf(H2[(k + 1) * PIT + rr], __ldg(W3 + k + 1), v1);
            v2 = fmaf(H2[(k + 2) * PIT + rr], __ldg(W3 + k + 2), v2);
            v3 = fmaf(H2[(k + 3) * PIT + rr], __ldg(W3 + k + 3), v3);
        }
        Ys[mlp][rr] = (v0 + v1) + (v2 + v3);
    }
    __syncthreads();

    // ---- epilogue: MIMICS physics, analytically reduced quadrature ----
    if (t < TILE) {
        int s = base + t;

        float inv = 1.0f / qsum[0];
        float S1 = qsum[1] * inv, S2 = qsum[2] * inv, S3 = qsum[3] * inv;

        const float LN10 = 2.302585093f;
        float Nb = __expf((2.0f + 3.0f * sigm(pf_nb)) * LN10);
        float Nl = __expf((3.0f + 3.0f * sigm(pf_nl)) * LN10);
        float dens = Nb * 1e-4f + Nl * 1e-6f;

        float mg   = 0.05f + 0.75f * sigm(pf_mg);
        float epsv = 1.5f + 20.0f * mg;
        float Kv   = (epsv - 1.0f) / (epsv + 2.0f);
        float Kv2  = Kv * Kv;

        float sm = 0.01f * (0.5f + 5.5f * sigm(pf_s));
        float kw = 2.0f * PI * (5.405e9f / 2.998e8f);
        float tt = 2.0f * kw * sm;
        float c_r = tt * tt;

        float m_v   = 0.93f * sigm(Ys[0][t]);
        float delta = 0.05f * tanh_acc(Ys[1][t]);   // direct output: exact tanh
        float eps_g = 3.0f + 25.0f * m_v + 10.0f * m_v * m_v;

        float ti = pf_th * (PI / 180.0f);
        float ct, st;
        __sincosf(ti, &st, &ct);
        float ct2 = ct * ct, st2 = st * st;

        float crown_vv = Kv2 * (ct2 * ct2 * S1 + 3.0f * ct2 * st2 * S2
                                + 0.375f * st2 * st2 * S3);
        float crown_vh = Kv2 * (0.5f * ct2 * S2 + 0.125f * st2 * S3);

        float root  = sqrtf(eps_g - st2);
        float r_v   = (eps_g * ct - root) / (eps_g * ct + root);
        float gamma = r_v * r_v;
        float rough = __expf(-c_r * ct2);
        float ground = gamma * rough * ct2;

        float svv = dens * crown_vv + ground;
        float svh = dens * crown_vh + 0.05f * ground;

        const float ILN10_10 = 4.342944819f;   // 10 / ln(10)
        out[0 * N_TOT + s] = m_v;
        out[1 * N_TOT + s] = delta;
        out[2 * N_TOT + s] = m_v + delta;
        out[3 * N_TOT + s] = __logf(svv + 1e-12f) * ILN10_10;
        out[4 * N_TOT + s] = __logf(svh + 1e-12f) * ILN10_10;
        out[5 * N_TOT + s] = eps_g;
    }
}

extern "C" void kernel_launch(void* const* d_in, const int* in_sizes, int n_in,
                              void* d_out, int out_size) {
    // inputs: 0 X, 1 theta_inc_deg, 2 vv_db_observed (unused),
    // 3 Wp1, 4 bp1, 5 Wp2, 6 bp2, 7 Wp3, 8 bp3,
    // 9 Wc1, 10 bc1, 11 Wc2, 12 bc2, 13 Wc3, 14 bc3,
    // 15 nb_raw, 16 nl_raw, 17 so_raw, 18 mg_raw, 19 s_raw
    (void)in_sizes; (void)n_in; (void)out_size;

    pinn_kernel<<<NBLK, NTHR>>>(
        (const float*)d_in[0], (const float*)d_in[1],
        (const float*)d_in[3], (const float*)d_in[4],
        (const float*)d_in[5], (const float*)d_in[6],
        (const float*)d_in[7], (const float*)d_in[8],
        (const float*)d_in[9], (const float*)d_in[10],
        (const float*)d_in[11], (const float*)d_in[12],
        (const float*)d_in[13], (const float*)d_in[14],
        (const float*)d_in[15], (const float*)d_in[16],
        (const float*)d_in[17], (const float*)d_in[18],
        (const float*)d_in[19],
        (float*)d_out);
}